// round 12
// baseline (speedup 1.0000x reference)
#include <cuda_runtime.h>
#include <cstdint>

// ---------------- problem constants ----------------
#define BATCH 16
#define C1    256
#define CH    128
#define HW    64
#define NPIX  (HW*HW)
#define INV_T (1.0f/16.0f)

// ---------------- scratch ----------------
__device__ uint32_t g_xt[BATCH * C1 * NPIX];   // x as tf32 bits
__device__ uint32_t g_y1[BATCH * CH * NPIX];   // y1 as tf32 bits
__device__ uint32_t g_y2[BATCH * C1 * NPIX];   // y2 as tf32 bits
__device__ float    g_sc[BATCH * C1 * C1];     // scores K-half 0 -> attn (tf32 bits)
__device__ float    g_scp[BATCH * C1 * C1];    // scores K-half 1 (partial)
__device__ float    g_w1p[CH * C1 * 9];        // tf32-bit weights [ci][tap][co]
__device__ float    g_w2p[C1 * CH * 9];
__device__ float    g_scale1[CH], g_shift1[CH];
__device__ float    g_scale2[C1], g_shift2[C1];

__constant__ int c_ti[3] = {0, 0, 1};
__constant__ int c_tj[3] = {0, 1, 1};

// ---------------- helpers ----------------
__device__ __forceinline__ uint32_t f2tf32(float f) {
    uint32_t u;
    asm("cvt.rna.tf32.f32 %0, %1;" : "=r"(u) : "f"(f));
    return u;
}

__device__ __forceinline__ void mma_tf32(float c[4], const uint32_t a[4],
                                         uint32_t b0, uint32_t b1) {
    asm volatile(
        "mma.sync.aligned.m16n8k8.row.col.f32.tf32.tf32.f32 "
        "{%0,%1,%2,%3}, {%4,%5,%6,%7}, {%8,%9}, {%0,%1,%2,%3};"
        : "+f"(c[0]), "+f"(c[1]), "+f"(c[2]), "+f"(c[3])
        : "r"(a[0]), "r"(a[1]), "r"(a[2]), "r"(a[3]), "r"(b0), "r"(b1));
}

__device__ __forceinline__ float silu(float y) {
    return y / (1.0f + __expf(-y));
}

__device__ __forceinline__ uint32_t smem_u32(const void* p) {
    return (uint32_t)__cvta_generic_to_shared(p);
}
__device__ __forceinline__ void cp16(uint32_t dst, const void* src) {
    asm volatile("cp.async.cg.shared.global [%0], [%1], 16;" :: "r"(dst), "l"(src));
}
__device__ __forceinline__ void cp16z(uint32_t dst, const void* src, int sz) {
    asm volatile("cp.async.cg.shared.global [%0], [%1], 16, %2;" :: "r"(dst), "l"(src), "r"(sz));
}
__device__ __forceinline__ void cp_commit() { asm volatile("cp.async.commit_group;"); }
template<int N> __device__ __forceinline__ void cp_wait() {
    asm volatile("cp.async.wait_group %0;" :: "n"(N));
}

// ---------------- BN fold ----------------
__global__ void fold_bn(const float* __restrict__ g1, const float* __restrict__ b1,
                        const float* __restrict__ m1, const float* __restrict__ v1,
                        const float* __restrict__ g2, const float* __restrict__ b2,
                        const float* __restrict__ m2, const float* __restrict__ v2)
{
    int i = threadIdx.x;
    if (i < CH) {
        float s = g1[i] * rsqrtf(v1[i] + 1e-5f);
        g_scale1[i] = s;
        g_shift1[i] = b1[i] - m1[i] * s;
    }
    if (i < C1) {
        float s = g2[i] * rsqrtf(v2[i] + 1e-5f);
        g_scale2[i] = s;
        g_shift2[i] = b2[i] - m2[i] * s;
    }
}

// ---------------- weight repack: [co][ci][t] -> [ci][t][co], tf32 bits ----------------
__global__ void repack_w(const float* __restrict__ w, float* __restrict__ wp,
                         int Cout, int Cin)
{
    int i = blockIdx.x * 256 + threadIdx.x;
    int total = Cout * Cin * 9;
    if (i < total) {
        int co = i / (Cin * 9);
        int ci = (i / 9) % Cin;
        int t  = i % 9;
        wp[(ci * 9 + t) * Cout + co] = __uint_as_float(f2tf32(w[i]));
    }
}

// ---------------- bulk fp32 -> tf32 bits ----------------
__global__ void cvt_to_tf32(const float4* __restrict__ src, uint4* __restrict__ dst, int n4)
{
    int i = blockIdx.x * 256 + threadIdx.x;
    if (i < n4) {
        float4 v = src[i];
        uint4 u;
        u.x = f2tf32(v.x); u.y = f2tf32(v.y);
        u.z = f2tf32(v.z); u.w = f2tf32(v.w);
        dst[i] = u;
    }
}

// ---------------- conv 3x3 same + BN + SiLU  (tf32 mma, cp.async 2-stage) ----------------
// Block: 64 cout x 8 rows x 64 px. 8 warps: warp wid owns row h0+wid, full 64 co.
// Warp tile: 64 cout x 64 px = 4 m-tiles x 8 n-tiles m16n8k8. K-chunk = 8 cin.
// s_in row layout: pixel gw stored at col gw+4 (cols 4..67); zero halo at cols 3 and 68.
template<int CIN>
__global__ void __launch_bounds__(256)
conv3x3_mma(const uint32_t* __restrict__ in, const float* __restrict__ wp,
            const float* __restrict__ scale, const float* __restrict__ shift,
            uint32_t* __restrict__ out, int Cout)
{
    const int b   = blockIdx.z;
    const int h0  = blockIdx.y * 8;
    const int co0 = blockIdx.x * 64;
    const int tid  = threadIdx.x;
    const int wid  = tid >> 5;          // row within tile, 0..7
    const int lane = tid & 31;
    const int g  = lane >> 2;
    const int tg = lane & 3;

    __shared__ uint32_t s_in[2][80 * 72];   // [(r*8+ci)*72 + col], r = 0..9 (h0-1..h0+8)
    __shared__ uint32_t s_w[2][72 * 72];    // [(t*8+ci)*72 + co]

    float acc[4][8][4];
    #pragma unroll
    for (int mt = 0; mt < 4; mt++)
        #pragma unroll
        for (int nt = 0; nt < 8; nt++)
            #pragma unroll
            for (int r = 0; r < 4; r++) acc[mt][nt][r] = 0.f;

    // zero halo cols (3, 68) for all 80 rows x both stages
    for (int i = tid; i < 320; i += 256) {
        int buf = i / 160;
        int rem = i % 160;
        int r   = rem >> 1;
        s_in[buf][r * 72 + ((rem & 1) ? 68 : 3)] = 0;
    }

    const uint32_t* inb = in + (size_t)b * CIN * NPIX;
    const uint32_t* wpb = (const uint32_t*)wp;

    const int e_row  = tid >> 4;        // 0..15
    const int e_cseg = (tid & 15) * 4;

    auto issue_chunk = [&](int ci0, int buf) {
        // input: 80 rows (r*8+ci) x 64 cols, zero-fill OOB rows
        uint32_t in_base = smem_u32(&s_in[buf][0]);
        #pragma unroll
        for (int p = 0; p < 5; p++) {
            int ridx = p * 16 + e_row;            // 0..79
            int r  = ridx >> 3;
            int ci = ridx & 7;
            int gh = h0 + r - 1;
            bool valid = (unsigned)gh < (unsigned)HW;
            int ghc = valid ? gh : 0;
            const uint32_t* src = inb + ((ci0 + ci) * HW + ghc) * HW + e_cseg;
            cp16z(in_base + (ridx * 72 + 4 + e_cseg) * 4, src, valid ? 16 : 0);
        }
        // weights: 72 rows (t*8+ci) x 64 cols
        uint32_t w_base = smem_u32(&s_w[buf][0]);
        #pragma unroll
        for (int p = 0; p < 5; p++) {
            int ridx = p * 16 + e_row;            // 0..79, guard <72
            if (ridx < 72) {
                int t  = ridx >> 3;
                int ci = ridx & 7;
                const uint32_t* src = wpb + ((size_t)(ci0 + ci) * 9 + t) * Cout + co0 + e_cseg;
                cp16(w_base + (ridx * 72 + e_cseg) * 4, src);
            }
        }
    };

    const int NCH = CIN / 8;
    issue_chunk(0, 0);
    cp_commit();

    for (int c = 0; c < NCH; c++) {
        if (c + 1 < NCH) {
            issue_chunk((c + 1) * 8, (c + 1) & 1);
            cp_commit();
            cp_wait<1>();
        } else {
            cp_wait<0>();
        }
        __syncthreads();

        const uint32_t* si = s_in[c & 1];
        const uint32_t* sw = s_w[c & 1];

        #pragma unroll
        for (int t = 0; t < 9; t++) {
            const int kh = t / 3, kw = t % 3;
            uint32_t a[4][4];
            #pragma unroll
            for (int mt = 0; mt < 4; mt++) {
                int base = mt * 16;
                a[mt][0] = sw[(t * 8 + tg) * 72 + base + g];
                a[mt][1] = sw[(t * 8 + tg) * 72 + base + g + 8];
                a[mt][2] = sw[(t * 8 + tg + 4) * 72 + base + g];
                a[mt][3] = sw[(t * 8 + tg + 4) * 72 + base + g + 8];
            }
            const int rr = wid + kh;   // 0..9
            #pragma unroll
            for (int nt = 0; nt < 8; nt++) {
                int col = 3 + nt * 8 + g + kw;   // gw = px+kw-1 at col gw+4
                uint32_t b0 = si[(rr * 8 + tg) * 72 + col];
                uint32_t b1 = si[(rr * 8 + tg + 4) * 72 + col];
                #pragma unroll
                for (int mt = 0; mt < 4; mt++)
                    mma_tf32(acc[mt][nt], a[mt], b0, b1);
            }
        }
        __syncthreads();
    }

    // ---- epilogue: BN + SiLU, store tf32 bits ----
    const int h = h0 + wid;
    #pragma unroll
    for (int mt = 0; mt < 4; mt++) {
        int coA = co0 + mt * 16 + g;
        int coB = coA + 8;
        float scA = scale[coA], shA = shift[coA];
        float scB = scale[coB], shB = shift[coB];
        uint32_t* rowA = out + (((size_t)b * Cout + coA) * HW + h) * HW;
        uint32_t* rowB = out + (((size_t)b * Cout + coB) * HW + h) * HW;
        #pragma unroll
        for (int nt = 0; nt < 8; nt++) {
            int px = nt * 8 + tg * 2;
            uint2 vA, vB;
            vA.x = f2tf32(silu(acc[mt][nt][0] * scA + shA));
            vA.y = f2tf32(silu(acc[mt][nt][1] * scA + shA));
            vB.x = f2tf32(silu(acc[mt][nt][2] * scB + shB));
            vB.y = f2tf32(silu(acc[mt][nt][3] * scB + shB));
            *(uint2*)&rowA[px] = vA;
            *(uint2*)&rowB[px] = vB;
        }
    }
}

// ---------------- gram: scores[b] = (Q/T) Q^T, symmetric 128x128 tiles, K-split 2 ----------------
// Grid (3 tiles, 2 k-halves, BATCH). 8 warps: warp tile 64c x 32d (m=4, n=4).
__global__ void __launch_bounds__(256)
gram_mma(const uint32_t* __restrict__ y2, float* __restrict__ sc0, float* __restrict__ sc1)
{
    const int b  = blockIdx.z;
    const int ti = c_ti[blockIdx.x];
    const int tj = c_tj[blockIdx.x];
    const int c0 = ti * 128, d0 = tj * 128;
    const int k0 = blockIdx.y * (NPIX / 2);
    float* sc = blockIdx.y ? sc1 : sc0;
    const int tid  = threadIdx.x;
    const int wid  = tid >> 5;
    const int lane = tid & 31;
    const int g  = lane >> 2;
    const int tg = lane & 3;
    const int m_w = (wid & 1) * 64;
    const int n_w = (wid >> 1) * 32;

    __shared__ uint32_t sA[2][128 * 36];   // [c][k]
    __shared__ uint32_t sB[2][128 * 36];   // [d][k]

    float acc[4][4][4];
    #pragma unroll
    for (int mt = 0; mt < 4; mt++)
        #pragma unroll
        for (int nt = 0; nt < 4; nt++)
            #pragma unroll
            for (int r = 0; r < 4; r++) acc[mt][nt][r] = 0.f;

    const uint32_t* Q = y2 + (size_t)b * C1 * NPIX;

    auto issue_chunk = [&](int nk, int buf) {
        uint32_t a_base = smem_u32(&sA[buf][0]);
        uint32_t b_base = smem_u32(&sB[buf][0]);
        #pragma unroll
        for (int p = 0; p < 4; p++) {
            int idx  = p * 256 + tid;
            int row  = idx >> 3;          // 0..127
            int kseg = (idx & 7) * 4;
            cp16(a_base + (row * 36 + kseg) * 4, Q + (size_t)(c0 + row) * NPIX + nk + kseg);
            cp16(b_base + (row * 36 + kseg) * 4, Q + (size_t)(d0 + row) * NPIX + nk + kseg);
        }
    };

    issue_chunk(k0, 0);
    cp_commit();

    const int NCH = (NPIX / 2) / 32;
    for (int c = 0; c < NCH; c++) {
        if (c + 1 < NCH) {
            issue_chunk(k0 + (c + 1) * 32, (c + 1) & 1);
            cp_commit();
            cp_wait<1>();
        } else {
            cp_wait<0>();
        }
        __syncthreads();

        const uint32_t* a_s = sA[c & 1];
        const uint32_t* b_s = sB[c & 1];

        #pragma unroll
        for (int ks = 0; ks < 4; ks++) {
            int kb = ks * 8;
            uint32_t a[4][4];
            #pragma unroll
            for (int mt = 0; mt < 4; mt++) {
                int base = m_w + mt * 16;
                a[mt][0] = a_s[(base + g) * 36 + kb + tg];
                a[mt][1] = a_s[(base + g + 8) * 36 + kb + tg];
                a[mt][2] = a_s[(base + g) * 36 + kb + tg + 4];
                a[mt][3] = a_s[(base + g + 8) * 36 + kb + tg + 4];
            }
            #pragma unroll
            for (int nt = 0; nt < 4; nt++) {
                uint32_t b0 = b_s[(n_w + nt * 8 + g) * 36 + kb + tg];
                uint32_t b1 = b_s[(n_w + nt * 8 + g) * 36 + kb + tg + 4];
                #pragma unroll
                for (int mt = 0; mt < 4; mt++)
                    mma_tf32(acc[mt][nt], a[mt], b0, b1);
            }
        }
        __syncthreads();
    }

    const bool mirror = (ti != tj);
    #pragma unroll
    for (int mt = 0; mt < 4; mt++) {
        int cA = c0 + m_w + mt * 16 + g;
        int cB = cA + 8;
        #pragma unroll
        for (int nt = 0; nt < 4; nt++) {
            int d = d0 + n_w + nt * 8 + tg * 2;
            float v0 = acc[mt][nt][0] * INV_T;
            float v1 = acc[mt][nt][1] * INV_T;
            float v2 = acc[mt][nt][2] * INV_T;
            float v3 = acc[mt][nt][3] * INV_T;
            *(float2*)&sc[((size_t)b * C1 + cA) * C1 + d] = make_float2(v0, v1);
            *(float2*)&sc[((size_t)b * C1 + cB) * C1 + d] = make_float2(v2, v3);
            if (mirror) {
                sc[((size_t)b * C1 + d)     * C1 + cA] = v0;
                sc[((size_t)b * C1 + d + 1) * C1 + cA] = v1;
                sc[((size_t)b * C1 + d)     * C1 + cB] = v2;
                sc[((size_t)b * C1 + d + 1) * C1 + cB] = v3;
            }
        }
    }
}

// ---------------- softmax: warp per row of 256, sums K-halves, writes tf32 bits ----------------
__global__ void __launch_bounds__(256)
softmax256(float* __restrict__ sc0, const float* __restrict__ sc1)
{
    const int row  = blockIdx.x * 8 + (threadIdx.x >> 5);
    const int lane = threadIdx.x & 31;
    float* p = sc0 + (size_t)row * C1;
    const float* q = sc1 + (size_t)row * C1;

    float4 v0 = *(const float4*)&p[lane * 4];
    float4 v1 = *(const float4*)&p[128 + lane * 4];
    float4 w0 = *(const float4*)&q[lane * 4];
    float4 w1 = *(const float4*)&q[128 + lane * 4];
    v0.x += w0.x; v0.y += w0.y; v0.z += w0.z; v0.w += w0.w;
    v1.x += w1.x; v1.y += w1.y; v1.z += w1.z; v1.w += w1.w;

    float m = fmaxf(fmaxf(fmaxf(v0.x, v0.y), fmaxf(v0.z, v0.w)),
                    fmaxf(fmaxf(v1.x, v1.y), fmaxf(v1.z, v1.w)));
    #pragma unroll
    for (int s = 16; s > 0; s >>= 1)
        m = fmaxf(m, __shfl_xor_sync(0xffffffffu, m, s));

    v0.x = __expf(v0.x - m); v0.y = __expf(v0.y - m);
    v0.z = __expf(v0.z - m); v0.w = __expf(v0.w - m);
    v1.x = __expf(v1.x - m); v1.y = __expf(v1.y - m);
    v1.z = __expf(v1.z - m); v1.w = __expf(v1.w - m);

    float s8 = v0.x + v0.y + v0.z + v0.w + v1.x + v1.y + v1.z + v1.w;
    #pragma unroll
    for (int s = 16; s > 0; s >>= 1)
        s8 += __shfl_xor_sync(0xffffffffu, s8, s);

    float inv = 1.0f / s8;
    uint4 u0, u1;
    u0.x = f2tf32(v0.x * inv); u0.y = f2tf32(v0.y * inv);
    u0.z = f2tf32(v0.z * inv); u0.w = f2tf32(v0.w * inv);
    u1.x = f2tf32(v1.x * inv); u1.y = f2tf32(v1.y * inv);
    u1.z = f2tf32(v1.z * inv); u1.w = f2tf32(v1.w * inv);

    *(uint4*)&p[lane * 4]       = u0;
    *(uint4*)&p[128 + lane * 4] = u1;
}

// ---------------- out[b] = attn[b] @ Q[b] + x, cp.async 2-stage ----------------
// Block tile 128c x 256n, K-chunk 32. 8 warps: warp tile 64c x 64n (m=4, n=8).
__global__ void __launch_bounds__(256)
attn_out_mma(const uint32_t* __restrict__ attn, const uint32_t* __restrict__ y2,
             const float* __restrict__ x, float* __restrict__ out)
{
    const int b  = blockIdx.z;
    const int c0 = blockIdx.y * 128;
    const int n0 = blockIdx.x * 256;
    const int tid  = threadIdx.x;
    const int wid  = tid >> 5;
    const int lane = tid & 31;
    const int g  = lane >> 2;
    const int tg = lane & 3;
    const int m_w = (wid & 1) * 64;
    const int n_w = (wid >> 1) * 64;

    __shared__ uint32_t sA[2][128 * 36];    // [c][k]
    __shared__ uint32_t sB[2][32 * 264];    // [k][n]

    float acc[4][8][4];
    #pragma unroll
    for (int mt = 0; mt < 4; mt++)
        #pragma unroll
        for (int nt = 0; nt < 8; nt++)
            #pragma unroll
            for (int r = 0; r < 4; r++) acc[mt][nt][r] = 0.f;

    const uint32_t* A = attn + (size_t)b * C1 * C1;
    const uint32_t* Q = y2 + (size_t)b * C1 * NPIX;

    auto issue_chunk = [&](int dk, int buf) {
        uint32_t a_base = smem_u32(&sA[buf][0]);
        uint32_t b_base = smem_u32(&sB[buf][0]);
        #pragma unroll
        for (int p = 0; p < 4; p++) {
            int idx  = p * 256 + tid;
            int row  = idx >> 3;          // 0..127
            int kseg = (idx & 7) * 4;
            cp16(a_base + (row * 36 + kseg) * 4, A + (size_t)(c0 + row) * C1 + dk + kseg);
        }
        #pragma unroll
        for (int p = 0; p < 8; p++) {
            int idx  = p * 256 + tid;
            int row  = idx >> 6;          // 0..31
            int cseg = (idx & 63) * 4;    // 0..252
            cp16(b_base + (row * 264 + cseg) * 4, Q + (size_t)(dk + row) * NPIX + n0 + cseg);
        }
    };

    issue_chunk(0, 0);
    cp_commit();

    const int NCH = C1 / 32;
    for (int c = 0; c < NCH; c++) {
        if (c + 1 < NCH) {
            issue_chunk((c + 1) * 32, (c + 1) & 1);
            cp_commit();
            cp_wait<1>();
        } else {
            cp_wait<0>();
        }
        __syncthreads();

        const uint32_t* a_s = sA[c & 1];
        const uint32_t* b_s = sB[c & 1];

        #pragma unroll
        for (int ks = 0; ks < 4; ks++) {
            int kb = ks * 8;
            uint32_t a[4][4];
            #pragma unroll
            for (int mt = 0; mt < 4; mt++) {
                int base = m_w + mt * 16;
                a[mt][0] = a_s[(base + g) * 36 + kb + tg];
                a[mt][1] = a_s[(base + g + 8) * 36 + kb + tg];
                a[mt][2] = a_s[(base + g) * 36 + kb + tg + 4];
                a[mt][3] = a_s[(base + g + 8) * 36 + kb + tg + 4];
            }
            #pragma unroll
            for (int nt = 0; nt < 8; nt++) {
                int nn = n_w + nt * 8 + g;
                uint32_t b0 = b_s[(kb + tg) * 264 + nn];
                uint32_t b1 = b_s[(kb + tg + 4) * 264 + nn];
                #pragma unroll
                for (int mt = 0; mt < 4; mt++)
                    mma_tf32(acc[mt][nt], a[mt], b0, b1);
            }
        }
        __syncthreads();
    }

    #pragma unroll
    for (int mt = 0; mt < 4; mt++) {
        int cA = c0 + m_w + mt * 16 + g;
        int cB = cA + 8;
        #pragma unroll
        for (int nt = 0; nt < 8; nt++) {
            int n = n0 + n_w + nt * 8 + tg * 2;
            size_t iA = ((size_t)b * C1 + cA) * NPIX + n;
            size_t iB = ((size_t)b * C1 + cB) * NPIX + n;
            float2 xA = *(const float2*)&x[iA];
            float2 xB = *(const float2*)&x[iB];
            *(float2*)&out[iA] = make_float2(acc[mt][nt][0] + xA.x, acc[mt][nt][1] + xA.y);
            *(float2*)&out[iB] = make_float2(acc[mt][nt][2] + xB.x, acc[mt][nt][3] + xB.y);
        }
    }
}

// ---------------- launch ----------------
extern "C" void kernel_launch(void* const* d_in, const int* in_sizes, int n_in,
                              void* d_out, int out_size)
{
    const float* x  = (const float*)d_in[0];
    const float* w1 = (const float*)d_in[1];
    const float* g1 = (const float*)d_in[2];
    const float* b1 = (const float*)d_in[3];
    const float* m1 = (const float*)d_in[4];
    const float* v1 = (const float*)d_in[5];
    const float* w2 = (const float*)d_in[6];
    const float* g2 = (const float*)d_in[7];
    const float* b2 = (const float*)d_in[8];
    const float* m2 = (const float*)d_in[9];
    const float* v2 = (const float*)d_in[10];
    float* out = (float*)d_out;

    uint32_t *xtp, *y1p, *y2p;
    float *scp, *scpp, *w1p, *w2p, *sc1p, *sh1p, *sc2p, *sh2p;
    cudaGetSymbolAddress((void**)&xtp,  g_xt);
    cudaGetSymbolAddress((void**)&y1p,  g_y1);
    cudaGetSymbolAddress((void**)&y2p,  g_y2);
    cudaGetSymbolAddress((void**)&scp,  g_sc);
    cudaGetSymbolAddress((void**)&scpp, g_scp);
    cudaGetSymbolAddress((void**)&w1p,  g_w1p);
    cudaGetSymbolAddress((void**)&w2p,  g_w2p);
    cudaGetSymbolAddress((void**)&sc1p, g_scale1);
    cudaGetSymbolAddress((void**)&sh1p, g_shift1);
    cudaGetSymbolAddress((void**)&sc2p, g_scale2);
    cudaGetSymbolAddress((void**)&sh2p, g_shift2);

    fold_bn<<<1, 256>>>(g1, b1, m1, v1, g2, b2, m2, v2);

    int nw1 = CH * C1 * 9;
    repack_w<<<(nw1 + 255) / 256, 256>>>(w1, w1p, CH, C1);
    repack_w<<<(nw1 + 255) / 256, 256>>>(w2, w2p, C1, CH);

    int n4 = BATCH * C1 * NPIX / 4;
    cvt_to_tf32<<<(n4 + 255) / 256, 256>>>((const float4*)x, (uint4*)xtp, n4);

    conv3x3_mma<C1><<<dim3(CH / 64, HW / 8, BATCH), 256>>>(xtp, w1p, sc1p, sh1p, y1p, CH);
    conv3x3_mma<CH><<<dim3(C1 / 64, HW / 8, BATCH), 256>>>(y1p, w2p, sc2p, sh2p, y2p, C1);

    gram_mma<<<dim3(3, 2, BATCH), 256>>>(y2p, scp, scpp);
    softmax256<<<BATCH * C1 / 8, 256>>>(scp, scpp);
    attn_out_mma<<<dim3(NPIX / 256, C1 / 128, BATCH), 256>>>((const uint32_t*)scp, y2p, x, out);
}

// round 13
// speedup vs baseline: 1.1037x; 1.1037x over previous
#include <cuda_runtime.h>
#include <cstdint>

// ---------------- problem constants ----------------
#define BATCH 16
#define C1    256
#define CH    128
#define HW    64
#define NPIX  (HW*HW)
#define INV_T (1.0f/16.0f)

// ---------------- scratch ----------------
__device__ uint32_t g_xt[BATCH * C1 * NPIX];   // x as tf32 bits
__device__ uint32_t g_y1[BATCH * CH * NPIX];   // y1 as tf32 bits
__device__ uint32_t g_y2[BATCH * C1 * NPIX];   // y2 as tf32 bits
__device__ float    g_sc[BATCH * C1 * C1];     // scores K-half 0 -> attn (tf32 bits)
__device__ float    g_scp[BATCH * C1 * C1];    // scores K-half 1 (partial)
__device__ float    g_w1p[CH * C1 * 9];        // tf32-bit weights [ci][tap][co]
__device__ float    g_w2p[C1 * CH * 9];
__device__ float    g_scale1[CH], g_shift1[CH];
__device__ float    g_scale2[C1], g_shift2[C1];

__constant__ int c_ti[3] = {0, 0, 1};
__constant__ int c_tj[3] = {0, 1, 1};

// ---------------- helpers ----------------
__device__ __forceinline__ uint32_t f2tf32(float f) {
    uint32_t u;
    asm("cvt.rna.tf32.f32 %0, %1;" : "=r"(u) : "f"(f));
    return u;
}

__device__ __forceinline__ void mma_tf32(float c[4], const uint32_t a[4],
                                         uint32_t b0, uint32_t b1) {
    asm volatile(
        "mma.sync.aligned.m16n8k8.row.col.f32.tf32.tf32.f32 "
        "{%0,%1,%2,%3}, {%4,%5,%6,%7}, {%8,%9}, {%0,%1,%2,%3};"
        : "+f"(c[0]), "+f"(c[1]), "+f"(c[2]), "+f"(c[3])
        : "r"(a[0]), "r"(a[1]), "r"(a[2]), "r"(a[3]), "r"(b0), "r"(b1));
}

__device__ __forceinline__ float silu(float y) {
    return y / (1.0f + __expf(-y));
}

__device__ __forceinline__ uint32_t smem_u32(const void* p) {
    return (uint32_t)__cvta_generic_to_shared(p);
}
__device__ __forceinline__ void cp16(uint32_t dst, const void* src) {
    asm volatile("cp.async.cg.shared.global [%0], [%1], 16;" :: "r"(dst), "l"(src));
}
__device__ __forceinline__ void cp16z(uint32_t dst, const void* src, int sz) {
    asm volatile("cp.async.cg.shared.global [%0], [%1], 16, %2;" :: "r"(dst), "l"(src), "r"(sz));
}
__device__ __forceinline__ void cp_commit() { asm volatile("cp.async.commit_group;"); }
template<int N> __device__ __forceinline__ void cp_wait() {
    asm volatile("cp.async.wait_group %0;" :: "n"(N));
}

// ---------------- BN fold ----------------
__global__ void fold_bn(const float* __restrict__ g1, const float* __restrict__ b1,
                        const float* __restrict__ m1, const float* __restrict__ v1,
                        const float* __restrict__ g2, const float* __restrict__ b2,
                        const float* __restrict__ m2, const float* __restrict__ v2)
{
    int i = threadIdx.x;
    if (i < CH) {
        float s = g1[i] * rsqrtf(v1[i] + 1e-5f);
        g_scale1[i] = s;
        g_shift1[i] = b1[i] - m1[i] * s;
    }
    if (i < C1) {
        float s = g2[i] * rsqrtf(v2[i] + 1e-5f);
        g_scale2[i] = s;
        g_shift2[i] = b2[i] - m2[i] * s;
    }
}

// ---------------- weight repack: [co][ci][t] -> [ci][t][co], tf32 bits ----------------
__global__ void repack_w(const float* __restrict__ w, float* __restrict__ wp,
                         int Cout, int Cin)
{
    int i = blockIdx.x * 256 + threadIdx.x;
    int total = Cout * Cin * 9;
    if (i < total) {
        int co = i / (Cin * 9);
        int ci = (i / 9) % Cin;
        int t  = i % 9;
        wp[(ci * 9 + t) * Cout + co] = __uint_as_float(f2tf32(w[i]));
    }
}

// ---------------- bulk fp32 -> tf32 bits ----------------
__global__ void cvt_to_tf32(const float4* __restrict__ src, uint4* __restrict__ dst, int n4)
{
    int i = blockIdx.x * 256 + threadIdx.x;
    if (i < n4) {
        float4 v = src[i];
        uint4 u;
        u.x = f2tf32(v.x); u.y = f2tf32(v.y);
        u.z = f2tf32(v.z); u.w = f2tf32(v.w);
        dst[i] = u;
    }
}

// ---------------- conv 3x3 same + BN + SiLU  (tf32 mma, cp.async 2-stage) ----------------
// Block: 64 cout x 4 rows x 64 px. 8 warps: wid&1 -> co half, wid>>1 -> row.
// Warp tile: 32 cout x 64 px = 2 m-tiles x 8 n-tiles m16n8k8. K-chunk = 8 cin.
// s_in row layout: pixel gw stored at col gw+4 (cols 4..67); zero halo at cols 3 and 68.
template<int CIN>
__global__ void __launch_bounds__(256)
conv3x3_mma(const uint32_t* __restrict__ in, const float* __restrict__ wp,
            const float* __restrict__ scale, const float* __restrict__ shift,
            uint32_t* __restrict__ out, int Cout)
{
    const int b   = blockIdx.z;
    const int h0  = blockIdx.y * 4;
    const int co0 = blockIdx.x * 64;
    const int tid  = threadIdx.x;
    const int wid  = tid >> 5;
    const int lane = tid & 31;
    const int g  = lane >> 2;
    const int tg = lane & 3;
    const int co_w = (wid & 1) * 32;
    const int r_w  = wid >> 1;          // 0..3

    __shared__ uint32_t s_in[2][48 * 72];
    __shared__ uint32_t s_w[2][72 * 72];

    float acc[2][8][4];
    #pragma unroll
    for (int mt = 0; mt < 2; mt++)
        #pragma unroll
        for (int nt = 0; nt < 8; nt++)
            #pragma unroll
            for (int r = 0; r < 4; r++) acc[mt][nt][r] = 0.f;

    // zero halo cols (3, 68) for all 48 rows x both stages
    if (tid < 192) {
        int buf = tid / 96;
        int rem = tid % 96;
        int r   = rem >> 1;
        s_in[buf][r * 72 + ((rem & 1) ? 68 : 3)] = 0;
    }

    const uint32_t* inb = in + (size_t)b * CIN * NPIX;
    const uint32_t* wpb = (const uint32_t*)wp;

    const int e_row  = tid >> 4;        // 0..15
    const int e_cseg = (tid & 15) * 4;

    auto issue_chunk = [&](int ci0, int buf) {
        // input: 48 rows x 64 cols (16B ops, zero-fill for OOB rows)
        uint32_t in_base = smem_u32(&s_in[buf][0]);
        #pragma unroll
        for (int p = 0; p < 3; p++) {
            int ridx = p * 16 + e_row;            // 0..47
            int r  = ridx >> 3;
            int ci = ridx & 7;
            int gh = h0 + r - 1;
            bool valid = (unsigned)gh < (unsigned)HW;
            int ghc = valid ? gh : 0;
            const uint32_t* src = inb + ((ci0 + ci) * HW + ghc) * HW + e_cseg;
            cp16z(in_base + (ridx * 72 + 4 + e_cseg) * 4, src, valid ? 16 : 0);
        }
        // weights: 72 rows (t*8+ci) x 64 cols
        uint32_t w_base = smem_u32(&s_w[buf][0]);
        #pragma unroll
        for (int p = 0; p < 5; p++) {
            int ridx = p * 16 + e_row;            // 0..79, guard <72
            if (ridx < 72) {
                int t  = ridx >> 3;
                int ci = ridx & 7;
                const uint32_t* src = wpb + ((size_t)(ci0 + ci) * 9 + t) * Cout + co0 + e_cseg;
                cp16(w_base + (ridx * 72 + e_cseg) * 4, src);
            }
        }
    };

    const int NCH = CIN / 8;
    issue_chunk(0, 0);
    cp_commit();

    for (int c = 0; c < NCH; c++) {
        if (c + 1 < NCH) {
            issue_chunk((c + 1) * 8, (c + 1) & 1);
            cp_commit();
            cp_wait<1>();
        } else {
            cp_wait<0>();
        }
        __syncthreads();

        const uint32_t* si = s_in[c & 1];
        const uint32_t* sw = s_w[c & 1];

        #pragma unroll
        for (int t = 0; t < 9; t++) {
            const int kh = t / 3, kw = t % 3;
            uint32_t a[2][4];
            #pragma unroll
            for (int mt = 0; mt < 2; mt++) {
                int base = co_w + mt * 16;
                a[mt][0] = sw[(t * 8 + tg) * 72 + base + g];
                a[mt][1] = sw[(t * 8 + tg) * 72 + base + g + 8];
                a[mt][2] = sw[(t * 8 + tg + 4) * 72 + base + g];
                a[mt][3] = sw[(t * 8 + tg + 4) * 72 + base + g + 8];
            }
            const int rr = r_w + kh;
            #pragma unroll
            for (int nt = 0; nt < 8; nt++) {
                int col = 3 + nt * 8 + g + kw;   // gw = px+kw-1 stored at gw+4 = px+kw+3
                uint32_t b0 = si[(rr * 8 + tg) * 72 + col];
                uint32_t b1 = si[(rr * 8 + tg + 4) * 72 + col];
                mma_tf32(acc[0][nt], a[0], b0, b1);
                mma_tf32(acc[1][nt], a[1], b0, b1);
            }
        }
        __syncthreads();
    }

    // ---- epilogue: BN + SiLU, store tf32 bits ----
    const int h = h0 + r_w;
    #pragma unroll
    for (int mt = 0; mt < 2; mt++) {
        int coA = co0 + co_w + mt * 16 + g;
        int coB = coA + 8;
        float scA = scale[coA], shA = shift[coA];
        float scB = scale[coB], shB = shift[coB];
        uint32_t* rowA = out + (((size_t)b * Cout + coA) * HW + h) * HW;
        uint32_t* rowB = out + (((size_t)b * Cout + coB) * HW + h) * HW;
        #pragma unroll
        for (int nt = 0; nt < 8; nt++) {
            int px = nt * 8 + tg * 2;
            uint2 vA, vB;
            vA.x = f2tf32(silu(acc[mt][nt][0] * scA + shA));
            vA.y = f2tf32(silu(acc[mt][nt][1] * scA + shA));
            vB.x = f2tf32(silu(acc[mt][nt][2] * scB + shB));
            vB.y = f2tf32(silu(acc[mt][nt][3] * scB + shB));
            *(uint2*)&rowA[px] = vA;
            *(uint2*)&rowB[px] = vB;
        }
    }
}

// ---------------- gram: scores[b] = (Q/T) Q^T, symmetric 128x128 tiles, K-split 2 ----------------
// Grid (3 tiles, 2 k-halves, BATCH). 8 warps: warp tile 64c x 32d (m=4, n=4).
__global__ void __launch_bounds__(256)
gram_mma(const uint32_t* __restrict__ y2, float* __restrict__ sc0, float* __restrict__ sc1)
{
    const int b  = blockIdx.z;
    const int ti = c_ti[blockIdx.x];
    const int tj = c_tj[blockIdx.x];
    const int c0 = ti * 128, d0 = tj * 128;
    const int k0 = blockIdx.y * (NPIX / 2);
    float* sc = blockIdx.y ? sc1 : sc0;
    const int tid  = threadIdx.x;
    const int wid  = tid >> 5;
    const int lane = tid & 31;
    const int g  = lane >> 2;
    const int tg = lane & 3;
    const int m_w = (wid & 1) * 64;
    const int n_w = (wid >> 1) * 32;

    __shared__ uint32_t sA[2][128 * 36];   // [c][k]
    __shared__ uint32_t sB[2][128 * 36];   // [d][k]

    float acc[4][4][4];
    #pragma unroll
    for (int mt = 0; mt < 4; mt++)
        #pragma unroll
        for (int nt = 0; nt < 4; nt++)
            #pragma unroll
            for (int r = 0; r < 4; r++) acc[mt][nt][r] = 0.f;

    const uint32_t* Q = y2 + (size_t)b * C1 * NPIX;

    auto issue_chunk = [&](int nk, int buf) {
        uint32_t a_base = smem_u32(&sA[buf][0]);
        uint32_t b_base = smem_u32(&sB[buf][0]);
        #pragma unroll
        for (int p = 0; p < 4; p++) {
            int idx  = p * 256 + tid;
            int row  = idx >> 3;          // 0..127
            int kseg = (idx & 7) * 4;
            cp16(a_base + (row * 36 + kseg) * 4, Q + (size_t)(c0 + row) * NPIX + nk + kseg);
            cp16(b_base + (row * 36 + kseg) * 4, Q + (size_t)(d0 + row) * NPIX + nk + kseg);
        }
    };

    issue_chunk(k0, 0);
    cp_commit();

    const int NCH = (NPIX / 2) / 32;
    for (int c = 0; c < NCH; c++) {
        if (c + 1 < NCH) {
            issue_chunk(k0 + (c + 1) * 32, (c + 1) & 1);
            cp_commit();
            cp_wait<1>();
        } else {
            cp_wait<0>();
        }
        __syncthreads();

        const uint32_t* a_s = sA[c & 1];
        const uint32_t* b_s = sB[c & 1];

        #pragma unroll
        for (int ks = 0; ks < 4; ks++) {
            int kb = ks * 8;
            uint32_t a[4][4];
            #pragma unroll
            for (int mt = 0; mt < 4; mt++) {
                int base = m_w + mt * 16;
                a[mt][0] = a_s[(base + g) * 36 + kb + tg];
                a[mt][1] = a_s[(base + g + 8) * 36 + kb + tg];
                a[mt][2] = a_s[(base + g) * 36 + kb + tg + 4];
                a[mt][3] = a_s[(base + g + 8) * 36 + kb + tg + 4];
            }
            #pragma unroll
            for (int nt = 0; nt < 4; nt++) {
                uint32_t b0 = b_s[(n_w + nt * 8 + g) * 36 + kb + tg];
                uint32_t b1 = b_s[(n_w + nt * 8 + g) * 36 + kb + tg + 4];
                #pragma unroll
                for (int mt = 0; mt < 4; mt++)
                    mma_tf32(acc[mt][nt], a[mt], b0, b1);
            }
        }
        __syncthreads();
    }

    const bool mirror = (ti != tj);
    #pragma unroll
    for (int mt = 0; mt < 4; mt++) {
        int cA = c0 + m_w + mt * 16 + g;
        int cB = cA + 8;
        #pragma unroll
        for (int nt = 0; nt < 4; nt++) {
            int d = d0 + n_w + nt * 8 + tg * 2;
            float v0 = acc[mt][nt][0] * INV_T;
            float v1 = acc[mt][nt][1] * INV_T;
            float v2 = acc[mt][nt][2] * INV_T;
            float v3 = acc[mt][nt][3] * INV_T;
            *(float2*)&sc[((size_t)b * C1 + cA) * C1 + d] = make_float2(v0, v1);
            *(float2*)&sc[((size_t)b * C1 + cB) * C1 + d] = make_float2(v2, v3);
            if (mirror) {
                sc[((size_t)b * C1 + d)     * C1 + cA] = v0;
                sc[((size_t)b * C1 + d + 1) * C1 + cA] = v1;
                sc[((size_t)b * C1 + d)     * C1 + cB] = v2;
                sc[((size_t)b * C1 + d + 1) * C1 + cB] = v3;
            }
        }
    }
}

// ---------------- softmax: warp per row of 256, sums K-halves, writes tf32 bits ----------------
__global__ void __launch_bounds__(256)
softmax256(float* __restrict__ sc0, const float* __restrict__ sc1)
{
    const int row  = blockIdx.x * 8 + (threadIdx.x >> 5);
    const int lane = threadIdx.x & 31;
    float* p = sc0 + (size_t)row * C1;
    const float* q = sc1 + (size_t)row * C1;

    float4 v0 = *(const float4*)&p[lane * 4];
    float4 v1 = *(const float4*)&p[128 + lane * 4];
    float4 w0 = *(const float4*)&q[lane * 4];
    float4 w1 = *(const float4*)&q[128 + lane * 4];
    v0.x += w0.x; v0.y += w0.y; v0.z += w0.z; v0.w += w0.w;
    v1.x += w1.x; v1.y += w1.y; v1.z += w1.z; v1.w += w1.w;

    float m = fmaxf(fmaxf(fmaxf(v0.x, v0.y), fmaxf(v0.z, v0.w)),
                    fmaxf(fmaxf(v1.x, v1.y), fmaxf(v1.z, v1.w)));
    #pragma unroll
    for (int s = 16; s > 0; s >>= 1)
        m = fmaxf(m, __shfl_xor_sync(0xffffffffu, m, s));

    v0.x = __expf(v0.x - m); v0.y = __expf(v0.y - m);
    v0.z = __expf(v0.z - m); v0.w = __expf(v0.w - m);
    v1.x = __expf(v1.x - m); v1.y = __expf(v1.y - m);
    v1.z = __expf(v1.z - m); v1.w = __expf(v1.w - m);

    float s8 = v0.x + v0.y + v0.z + v0.w + v1.x + v1.y + v1.z + v1.w;
    #pragma unroll
    for (int s = 16; s > 0; s >>= 1)
        s8 += __shfl_xor_sync(0xffffffffu, s8, s);

    float inv = 1.0f / s8;
    uint4 u0, u1;
    u0.x = f2tf32(v0.x * inv); u0.y = f2tf32(v0.y * inv);
    u0.z = f2tf32(v0.z * inv); u0.w = f2tf32(v0.w * inv);
    u1.x = f2tf32(v1.x * inv); u1.y = f2tf32(v1.y * inv);
    u1.z = f2tf32(v1.z * inv); u1.w = f2tf32(v1.w * inv);

    *(uint4*)&p[lane * 4]       = u0;
    *(uint4*)&p[128 + lane * 4] = u1;
}

// ---------------- out[b] = attn[b] @ Q[b] + x, cp.async 2-stage ----------------
// Block tile 128c x 128n, K-chunk 32. 8 warps (2x4): warp tile 64c x 32n (m=4, n=4).
__global__ void __launch_bounds__(256)
attn_out_mma(const uint32_t* __restrict__ attn, const uint32_t* __restrict__ y2,
             const float* __restrict__ x, float* __restrict__ out)
{
    const int b  = blockIdx.z;
    const int c0 = blockIdx.y * 128;
    const int n0 = blockIdx.x * 128;
    const int tid  = threadIdx.x;
    const int wid  = tid >> 5;
    const int lane = tid & 31;
    const int g  = lane >> 2;
    const int tg = lane & 3;
    const int m_w = (wid & 1) * 64;
    const int n_w = (wid >> 1) * 32;

    __shared__ uint32_t sA[2][128 * 36];    // [c][k]
    __shared__ uint32_t sB[2][32 * 136];    // [k][n]

    float acc[4][4][4];
    #pragma unroll
    for (int mt = 0; mt < 4; mt++)
        #pragma unroll
        for (int nt = 0; nt < 4; nt++)
            #pragma unroll
            for (int r = 0; r < 4; r++) acc[mt][nt][r] = 0.f;

    const uint32_t* A = attn + (size_t)b * C1 * C1;
    const uint32_t* Q = y2 + (size_t)b * C1 * NPIX;

    auto issue_chunk = [&](int dk, int buf) {
        uint32_t a_base = smem_u32(&sA[buf][0]);
        uint32_t b_base = smem_u32(&sB[buf][0]);
        #pragma unroll
        for (int p = 0; p < 4; p++) {
            int idx  = p * 256 + tid;
            int row  = idx >> 3;          // 0..127
            int kseg = (idx & 7) * 4;
            cp16(a_base + (row * 36 + kseg) * 4, A + (size_t)(c0 + row) * C1 + dk + kseg);
        }
        #pragma unroll
        for (int p = 0; p < 4; p++) {
            int idx  = p * 256 + tid;
            int row  = idx >> 5;          // 0..31
            int cseg = (idx & 31) * 4;    // 0..124
            cp16(b_base + (row * 136 + cseg) * 4, Q + (size_t)(dk + row) * NPIX + n0 + cseg);
        }
    };

    issue_chunk(0, 0);
    cp_commit();

    const int NCH = C1 / 32;
    for (int c = 0; c < NCH; c++) {
        if (c + 1 < NCH) {
            issue_chunk((c + 1) * 32, (c + 1) & 1);
            cp_commit();
            cp_wait<1>();
        } else {
            cp_wait<0>();
        }
        __syncthreads();

        const uint32_t* a_s = sA[c & 1];
        const uint32_t* b_s = sB[c & 1];

        #pragma unroll
        for (int ks = 0; ks < 4; ks++) {
            int kb = ks * 8;
            uint32_t a[4][4];
            #pragma unroll
            for (int mt = 0; mt < 4; mt++) {
                int base = m_w + mt * 16;
                a[mt][0] = a_s[(base + g) * 36 + kb + tg];
                a[mt][1] = a_s[(base + g + 8) * 36 + kb + tg];
                a[mt][2] = a_s[(base + g) * 36 + kb + tg + 4];
                a[mt][3] = a_s[(base + g + 8) * 36 + kb + tg + 4];
            }
            #pragma unroll
            for (int nt = 0; nt < 4; nt++) {
                int nn = n_w + nt * 8 + g;
                uint32_t b0 = b_s[(kb + tg) * 136 + nn];
                uint32_t b1 = b_s[(kb + tg + 4) * 136 + nn];
                #pragma unroll
                for (int mt = 0; mt < 4; mt++)
                    mma_tf32(acc[mt][nt], a[mt], b0, b1);
            }
        }
        __syncthreads();
    }

    #pragma unroll
    for (int mt = 0; mt < 4; mt++) {
        int cA = c0 + m_w + mt * 16 + g;
        int cB = cA + 8;
        #pragma unroll
        for (int nt = 0; nt < 4; nt++) {
            int n = n0 + n_w + nt * 8 + tg * 2;
            size_t iA = ((size_t)b * C1 + cA) * NPIX + n;
            size_t iB = ((size_t)b * C1 + cB) * NPIX + n;
            float2 xA = *(const float2*)&x[iA];
            float2 xB = *(const float2*)&x[iB];
            *(float2*)&out[iA] = make_float2(acc[mt][nt][0] + xA.x, acc[mt][nt][1] + xA.y);
            *(float2*)&out[iB] = make_float2(acc[mt][nt][2] + xB.x, acc[mt][nt][3] + xB.y);
        }
    }
}

// ---------------- launch ----------------
extern "C" void kernel_launch(void* const* d_in, const int* in_sizes, int n_in,
                              void* d_out, int out_size)
{
    const float* x  = (const float*)d_in[0];
    const float* w1 = (const float*)d_in[1];
    const float* g1 = (const float*)d_in[2];
    const float* b1 = (const float*)d_in[3];
    const float* m1 = (const float*)d_in[4];
    const float* v1 = (const float*)d_in[5];
    const float* w2 = (const float*)d_in[6];
    const float* g2 = (const float*)d_in[7];
    const float* b2 = (const float*)d_in[8];
    const float* m2 = (const float*)d_in[9];
    const float* v2 = (const float*)d_in[10];
    float* out = (float*)d_out;

    uint32_t *xtp, *y1p, *y2p;
    float *scp, *scpp, *w1p, *w2p, *sc1p, *sh1p, *sc2p, *sh2p;
    cudaGetSymbolAddress((void**)&xtp,  g_xt);
    cudaGetSymbolAddress((void**)&y1p,  g_y1);
    cudaGetSymbolAddress((void**)&y2p,  g_y2);
    cudaGetSymbolAddress((void**)&scp,  g_sc);
    cudaGetSymbolAddress((void**)&scpp, g_scp);
    cudaGetSymbolAddress((void**)&w1p,  g_w1p);
    cudaGetSymbolAddress((void**)&w2p,  g_w2p);
    cudaGetSymbolAddress((void**)&sc1p, g_scale1);
    cudaGetSymbolAddress((void**)&sh1p, g_shift1);
    cudaGetSymbolAddress((void**)&sc2p, g_scale2);
    cudaGetSymbolAddress((void**)&sh2p, g_shift2);

    fold_bn<<<1, 256>>>(g1, b1, m1, v1, g2, b2, m2, v2);

    int nw1 = CH * C1 * 9;
    repack_w<<<(nw1 + 255) / 256, 256>>>(w1, w1p, CH, C1);
    repack_w<<<(nw1 + 255) / 256, 256>>>(w2, w2p, C1, CH);

    int n4 = BATCH * C1 * NPIX / 4;
    cvt_to_tf32<<<(n4 + 255) / 256, 256>>>((const float4*)x, (uint4*)xtp, n4);

    conv3x3_mma<C1><<<dim3(CH / 64, HW / 4, BATCH), 256>>>(xtp, w1p, sc1p, sh1p, y1p, CH);
    conv3x3_mma<CH><<<dim3(C1 / 64, HW / 4, BATCH), 256>>>(y1p, w2p, sc2p, sh2p, y2p, C1);

    gram_mma<<<dim3(3, 2, BATCH), 256>>>(y2p, scp, scpp);
    softmax256<<<BATCH * C1 / 8, 256>>>(scp, scpp);
    attn_out_mma<<<dim3(NPIX / 128, C1 / 128, BATCH), 256>>>((const uint32_t*)scp, y2p, x, out);
}